// round 3
// baseline (speedup 1.0000x reference)
#include <cuda_runtime.h>

// Residual VQ forward: x (B*T=16384, D=512), codebooks (Q=8, K=2048, D=512).
// Output layout (float32): [ quantized (16384*512) | indices as float (16384*8) | loss (1) ]
//
// Score replicates reference fp32 numerics:
//   d_k = fl( fl(a - 2*e_k) + c_k ),  a = ||r||^2 (16-lane LLVM-NEON reduce order),
//   e_k = sequential-k fp32 fma dot (Eigen order), c_k = ||c||^2 (same reduce order).
//   argmin: strict <, first (lowest) index wins ties.

#define NROWS 16384
#define DIMD  512
#define KSZ   2048
#define NQ    8

#define BM 128
#define BN 128
#define BK 16
#define TM 8
#define TN 8
#define BMP (BM + 4)
#define NBLK (NROWS / BM)   // 128

__device__ float  g_residual[NROWS * DIMD];
__device__ float  g_cnorm[NQ * KSZ];
__device__ double g_lpart[NQ * NBLK];

// ---------------------------------------------------------------------------
// Exact 16-lane reduce of sum(v[d]^2) over 512 contiguous floats, replicating
// LLVM NEON VF=4 x IC=4 vectorized reduction:
//   S_l = sum_j fma(v[16j+l]^2), j ascending
//   u_l = (S_l + S_{l+4}) + (S_{l+8} + S_{l+12}),  l = 0..3
//   result = (u0 + u1) + (u2 + u3)
__device__ __forceinline__ float sq_norm_16lane(const float* __restrict__ p) {
    float S[16];
#pragma unroll
    for (int l = 0; l < 16; l++) S[l] = 0.f;
#pragma unroll 4
    for (int j = 0; j < 32; j++) {
        const float4* q = (const float4*)(p + j * 16);
        float4 v0 = q[0], v1 = q[1], v2 = q[2], v3 = q[3];
        S[0]  = fmaf(v0.x, v0.x, S[0]);  S[1]  = fmaf(v0.y, v0.y, S[1]);
        S[2]  = fmaf(v0.z, v0.z, S[2]);  S[3]  = fmaf(v0.w, v0.w, S[3]);
        S[4]  = fmaf(v1.x, v1.x, S[4]);  S[5]  = fmaf(v1.y, v1.y, S[5]);
        S[6]  = fmaf(v1.z, v1.z, S[6]);  S[7]  = fmaf(v1.w, v1.w, S[7]);
        S[8]  = fmaf(v2.x, v2.x, S[8]);  S[9]  = fmaf(v2.y, v2.y, S[9]);
        S[10] = fmaf(v2.z, v2.z, S[10]); S[11] = fmaf(v2.w, v2.w, S[11]);
        S[12] = fmaf(v3.x, v3.x, S[12]); S[13] = fmaf(v3.y, v3.y, S[13]);
        S[14] = fmaf(v3.z, v3.z, S[14]); S[15] = fmaf(v3.w, v3.w, S[15]);
    }
    float u0 = (S[0] + S[4]) + (S[8]  + S[12]);
    float u1 = (S[1] + S[5]) + (S[9]  + S[13]);
    float u2 = (S[2] + S[6]) + (S[10] + S[14]);
    float u3 = (S[3] + S[7]) + (S[11] + S[15]);
    return (u0 + u1) + (u2 + u3);
}

// ---------------------------------------------------------------------------
__global__ void rvq_init(const float4* __restrict__ x, float4* __restrict__ outQ) {
    int i = blockIdx.x * blockDim.x + threadIdx.x;
    if (i < NROWS * DIMD / 4) {
        ((float4*)g_residual)[i] = x[i];
        outQ[i] = make_float4(0.f, 0.f, 0.f, 0.f);
    }
}

// ---------------------------------------------------------------------------
// cnorm: one thread per codebook row, exact 16-lane order.
__global__ void rvq_cnorm(const float* __restrict__ cb) {
    int r = blockIdx.x * blockDim.x + threadIdx.x;
    if (r >= NQ * KSZ) return;
    g_cnorm[r] = sq_norm_16lane(cb + (long long)r * DIMD);
}

// ---------------------------------------------------------------------------
// Fused per-level kernel: rownorm + distance GEMM + row argmin + gather/update.
__global__ __launch_bounds__(256, 1)
void rvq_level(const float* __restrict__ cb,   // this level's codebook (KSZ*DIMD)
               float* __restrict__ outQ,
               float* __restrict__ outIdx,     // may be null
               int level)
{
    __shared__ __align__(16) float As[BK][BMP];
    __shared__ __align__(16) float Bs[BK][BMP];
    __shared__ float  redV[BM][16];
    __shared__ int    redI[BM][16];
    __shared__ int    sBest[BM];
    __shared__ float  sRowNorm[BM];
    __shared__ double wsum[8];

    const int tid = threadIdx.x;
    const int tx = tid & 15;
    const int ty = tid >> 4;
    const int rowBase = blockIdx.x * BM;

    const float* __restrict__ cn = g_cnorm + level * KSZ;
    const float* __restrict__ resA = g_residual + (long long)rowBase * DIMD;

    // per-row squared norm of current residual, exact reference order
    if (tid < BM) {
        sRowNorm[tid] = sq_norm_16lane(resA + tid * DIMD);
    }

    float bestv[TM];
    int   besti[TM];
#pragma unroll
    for (int m = 0; m < TM; m++) { bestv[m] = 3.4e38f; besti[m] = 0; }

    // tile loader mapping: 128 rows x 16 cols fp32 = 512 float4; each thread owns 2
    const int jr0 = tid >> 2;               // 0..63
    const int jr1 = jr0 + 64;               // 64..127
    const int jc  = (tid & 3) * 4;          // 0,4,8,12

    float4 a0, a1, b0, b1;
    a0 = *(const float4*)(resA + jr0 * DIMD + jc);
    a1 = *(const float4*)(resA + jr1 * DIMD + jc);
    b0 = *(const float4*)(cb + jr0 * DIMD + jc);
    b1 = *(const float4*)(cb + jr1 * DIMD + jc);

    const int NSTEP = DIMD / BK;   // 32
    const int NCHUNK = KSZ / BN;   // 16

    float aR[TM];
    bool aLoaded = false;

    for (int nc = 0; nc < NCHUNK; nc++) {
        float acc[TM][TN];
#pragma unroll
        for (int m = 0; m < TM; m++)
#pragma unroll
            for (int n = 0; n < TN; n++) acc[m][n] = 0.f;

        for (int ds = 0; ds < NSTEP; ds++) {
            __syncthreads();
            As[jc + 0][jr0] = a0.x; As[jc + 1][jr0] = a0.y;
            As[jc + 2][jr0] = a0.z; As[jc + 3][jr0] = a0.w;
            As[jc + 0][jr1] = a1.x; As[jc + 1][jr1] = a1.y;
            As[jc + 2][jr1] = a1.z; As[jc + 3][jr1] = a1.w;
            Bs[jc + 0][jr0] = b0.x; Bs[jc + 1][jr0] = b0.y;
            Bs[jc + 2][jr0] = b0.z; Bs[jc + 3][jr0] = b0.w;
            Bs[jc + 0][jr1] = b1.x; Bs[jc + 1][jr1] = b1.y;
            Bs[jc + 2][jr1] = b1.z; Bs[jc + 3][jr1] = b1.w;
            __syncthreads();

            // prefetch next step
            int s = nc * NSTEP + ds + 1;
            if (s < NCHUNK * NSTEP) {
                int nn = s >> 5;          // NSTEP = 32
                int dd = s & 31;
                const float* pa = resA + dd * BK;
                const float* pb = cb + (long long)(nn * BN) * DIMD + dd * BK;
                a0 = *(const float4*)(pa + jr0 * DIMD + jc);
                a1 = *(const float4*)(pa + jr1 * DIMD + jc);
                b0 = *(const float4*)(pb + jr0 * DIMD + jc);
                b1 = *(const float4*)(pb + jr1 * DIMD + jc);
            }

#pragma unroll
            for (int k = 0; k < BK; k++) {
                float af[TM], bf[TN];
                *(float4*)&af[0] = *(float4*)&As[k][ty * TM + 0];
                *(float4*)&af[4] = *(float4*)&As[k][ty * TM + 4];
                *(float4*)&bf[0] = *(float4*)&Bs[k][tx * TN + 0];
                *(float4*)&bf[4] = *(float4*)&Bs[k][tx * TN + 4];
#pragma unroll
                for (int m = 0; m < TM; m++)
#pragma unroll
                    for (int n = 0; n < TN; n++)
                        acc[m][n] = fmaf(af[m], bf[n], acc[m][n]);
            }
        }

        if (!aLoaded) {   // sRowNorm valid (many __syncthreads since write)
#pragma unroll
            for (int m = 0; m < TM; m++) aR[m] = sRowNorm[ty * TM + m];
            aLoaded = true;
        }

        // chunk epilogue: d = fl(fl(a - 2e) + c), running argmin (k ascending)
        const int nBase = nc * BN + tx * TN;
        float cnr[TN];
#pragma unroll
        for (int n = 0; n < TN; n++) cnr[n] = cn[nBase + n];
#pragma unroll
        for (int m = 0; m < TM; m++) {
#pragma unroll
            for (int n = 0; n < TN; n++) {
                float t = fmaf(-2.f, acc[m][n], aR[m]);  // fl(a - 2e)
                float d = t + cnr[n];                    // fl(t + c)
                if (d < bestv[m]) { bestv[m] = d; besti[m] = nBase + n; }
            }
        }
    }

    // cross-thread per-row argmin (prefer smaller index on ties)
#pragma unroll
    for (int m = 0; m < TM; m++) {
        redV[ty * TM + m][tx] = bestv[m];
        redI[ty * TM + m][tx] = besti[m];
    }
    __syncthreads();
    if (tid < BM) {
        float bv = redV[tid][0];
        int   bi = redI[tid][0];
#pragma unroll
        for (int t = 1; t < 16; t++) {
            float v = redV[tid][t]; int ii = redI[tid][t];
            if (v < bv || (v == bv && ii < bi)) { bv = v; bi = ii; }
        }
        sBest[tid] = bi;
        if (outIdx) outIdx[(long long)(rowBase + tid) * NQ + level] = (float)bi;
    }
    __syncthreads();

    // gather chosen codewords, update residual + quantized, accumulate loss
    double lsum = 0.0;
    {
        const float4* cb4 = (const float4*)cb;
        float4* res4 = (float4*)g_residual;
        float4* outQ4 = (float4*)outQ;
        const int D4 = DIMD / 4;  // 128
        for (int e = tid; e < BM * D4; e += 256) {
            int r = e >> 7;
            int d = e & (D4 - 1);
            int k = sBest[r];
            long long off = (long long)(rowBase + r) * D4 + d;
            float4 q = cb4[k * D4 + d];
            float4 rv = res4[off];
            rv.x -= q.x; rv.y -= q.y; rv.z -= q.z; rv.w -= q.w;
            res4[off] = rv;
            float4 qa = outQ4[off];
            qa.x += q.x; qa.y += q.y; qa.z += q.z; qa.w += q.w;
            outQ4[off] = qa;
            lsum += (double)rv.x * rv.x + (double)rv.y * rv.y
                  + (double)rv.z * rv.z + (double)rv.w * rv.w;
        }
    }
#pragma unroll
    for (int o = 16; o > 0; o >>= 1)
        lsum += __shfl_down_sync(0xffffffffu, lsum, o);
    if ((tid & 31) == 0) wsum[tid >> 5] = lsum;
    __syncthreads();
    if (tid == 0) {
        double t = 0.0;
        for (int w = 0; w < 8; w++) t += wsum[w];
        g_lpart[level * NBLK + blockIdx.x] = t;   // deterministic partials
    }
}

// ---------------------------------------------------------------------------
// Straight-through estimator epilogue: out = fl(x + fl(q - x))
__global__ void rvq_ste(const float* __restrict__ x, float* __restrict__ outQ) {
    int i = blockIdx.x * blockDim.x + threadIdx.x;
    if (i < NROWS * DIMD) {
        float xv = x[i];
        float qv = outQ[i];
        outQ[i] = xv + (qv - xv);
    }
}

// ---------------------------------------------------------------------------
__global__ void rvq_finalize(float* __restrict__ outLoss) {
    if (threadIdx.x == 0 && blockIdx.x == 0) {
        double t = 0.0;
        for (int i = 0; i < NQ * NBLK; i++) t += g_lpart[i];
        double denom = 8.0 * (double)NROWS * (double)DIMD;
        *outLoss = (float)(t * 1.25 / denom);
    }
}

// ---------------------------------------------------------------------------
extern "C" void kernel_launch(void* const* d_in, const int* in_sizes, int n_in,
                              void* d_out, int out_size) {
    const float* x  = (const float*)d_in[0];
    const float* cb = (const float*)d_in[1];
    float* out = (float*)d_out;
    float* outQ = out;
    float* outIdx = (out_size >= NROWS * DIMD + NROWS * NQ) ? (out + NROWS * DIMD)
                                                            : (float*)0;

    rvq_init<<<(NROWS * DIMD / 4 + 255) / 256, 256>>>((const float4*)x, (float4*)outQ);
    rvq_cnorm<<<(NQ * KSZ + 255) / 256, 256>>>(cb);
    for (int l = 0; l < NQ; l++) {
        rvq_level<<<NBLK, 256>>>(cb + (long long)l * KSZ * DIMD, outQ, outIdx, l);
    }
    rvq_ste<<<(NROWS * DIMD + 255) / 256, 256>>>(x, outQ);
    if (out_size >= NROWS * DIMD + NROWS * NQ + 1) {
        rvq_finalize<<<1, 32>>>(out + NROWS * DIMD + NROWS * NQ);
    }
}